// round 6
// baseline (speedup 1.0000x reference)
#include <cuda_runtime.h>
#include <cuda_fp16.h>
#include <math.h>

// GATv2 (L=3, H=4, C=16, D=64), N=100000, E=1280000 (+N self loops).
// R6 design (= R5 with correct shfl masks):
//  - CSR by dst (hist+scan+scatter, once per launch)
//  - GEMM writes xl in fp16 (128B row) and xr in fp32
//  - fused agg: warp = 2 nodes x 2 edge-slots x 8 channel-lanes.
//    ALL shfls in/after the divergent edge loop use the half-warp mask.

#define NNODES 100000
#define NEDGES 1280000
#define DD 64
#define SCAN_BLK 512
#define SCAN_ELEM 8
#define SCAN_TILE (SCAN_BLK * SCAN_ELEM)  // 4096

__device__ __align__(128) __half g_xlh[NNODES * DD];
__device__ __align__(16) float g_xr[NNODES * DD];
__device__ __align__(16) float g_b0[NNODES * DD];
__device__ __align__(16) float g_b1[NNODES * DD];
__device__ int g_cnt[NNODES];
__device__ int g_tmp[NNODES];
__device__ int g_ofs[NNODES];
__device__ int g_rowptr[NNODES + 1];
__device__ int g_bsum[1024];
__device__ int g_ssrc[NEDGES];

// ------------------------- CSR build (once per launch) ----------------------
__global__ void k_cntzero(int n) {
    int i = blockIdx.x * blockDim.x + threadIdx.x;
    if (i < n) g_cnt[i] = 0;
}

__global__ void k_hist(const int* __restrict__ ei, int E) {
    int e = blockIdx.x * blockDim.x + threadIdx.x;
    if (e < E) atomicAdd(&g_cnt[ei[E + e]], 1);
}

__global__ __launch_bounds__(SCAN_BLK) void k_scan1(int n) {
    __shared__ int sh[SCAN_BLK];
    int blk = blockIdx.x;
    int base = blk * SCAN_TILE + threadIdx.x * SCAN_ELEM;
    int t = threadIdx.x;
    int v[SCAN_ELEM];
    int sum = 0;
#pragma unroll
    for (int i = 0; i < SCAN_ELEM; i++) {
        int idx = base + i;
        v[i] = (idx < n) ? g_cnt[idx] : 0;
        sum += v[i];
    }
    sh[t] = sum;
    __syncthreads();
    for (int o = 1; o < SCAN_BLK; o <<= 1) {
        int x = (t >= o) ? sh[t - o] : 0;
        __syncthreads();
        sh[t] += x;
        __syncthreads();
    }
    int run = (t > 0) ? sh[t - 1] : 0;
    if (t == SCAN_BLK - 1) g_bsum[blk] = sh[t];
#pragma unroll
    for (int i = 0; i < SCAN_ELEM; i++) {
        int idx = base + i;
        if (idx < n) g_tmp[idx] = run;
        run += v[i];
    }
}

__global__ __launch_bounds__(1024) void k_scan2(int nb) {
    __shared__ int sh[1024];
    int t = threadIdx.x;
    sh[t] = (t < nb) ? g_bsum[t] : 0;
    __syncthreads();
    for (int o = 1; o < 1024; o <<= 1) {
        int x = (t >= o) ? sh[t - o] : 0;
        __syncthreads();
        sh[t] += x;
        __syncthreads();
    }
    g_bsum[t] = (t > 0) ? sh[t - 1] : 0;
}

__global__ void k_scan3(int n, int E) {
    int i = blockIdx.x * blockDim.x + threadIdx.x;
    if (i < n) {
        int r = g_tmp[i] + g_bsum[i / SCAN_TILE];
        g_rowptr[i] = r;
        g_ofs[i] = r;
    }
    if (i == n) g_rowptr[n] = E;
}

__global__ void k_scatter(const int* __restrict__ ei, int E) {
    int e = blockIdx.x * blockDim.x + threadIdx.x;
    if (e < E) {
        int d = ei[E + e];
        int pos = atomicAdd(&g_ofs[d], 1);
        g_ssrc[pos] = ei[e];
    }
}

// ---------------------------------------------------------------------------
// GEMM: xl = x @ Wl (-> fp16), xr = x @ Wr (-> fp32).  K = 64.
// ---------------------------------------------------------------------------
__global__ __launch_bounds__(256) void k_gemm(const float* __restrict__ x,
                                              const float* __restrict__ Wl,
                                              const float* __restrict__ Wr,
                                              int n) {
    __shared__ float sWl[64][64];
    __shared__ float sWr[64][64];
    __shared__ float sxT[64][64];

    int nodeBase = blockIdx.x * 64;

    for (int i = threadIdx.x; i < 64 * 64; i += 256) {
        sWl[i >> 6][i & 63] = Wl[i];
        sWr[i >> 6][i & 63] = Wr[i];
        int r = i >> 6, c = i & 63;
        int node = nodeBase + r;
        float v = (node < n) ? x[(size_t)node * DD + c] : 0.f;
        sxT[c][r] = v;
    }
    __syncthreads();

    int local = threadIdx.x >> 2;
    int cg = (threadIdx.x & 3) << 4;

    float accL[16], accR[16];
#pragma unroll
    for (int c = 0; c < 16; c++) { accL[c] = 0.f; accR[c] = 0.f; }

#pragma unroll 4
    for (int k = 0; k < 64; k++) {
        float xv = sxT[k][local];
        const float4* wl = (const float4*)&sWl[k][cg];
        const float4* wr = (const float4*)&sWr[k][cg];
#pragma unroll
        for (int q = 0; q < 4; q++) {
            float4 a = wl[q];
            float4 b = wr[q];
            accL[q * 4 + 0] = fmaf(xv, a.x, accL[q * 4 + 0]);
            accL[q * 4 + 1] = fmaf(xv, a.y, accL[q * 4 + 1]);
            accL[q * 4 + 2] = fmaf(xv, a.z, accL[q * 4 + 2]);
            accL[q * 4 + 3] = fmaf(xv, a.w, accL[q * 4 + 3]);
            accR[q * 4 + 0] = fmaf(xv, b.x, accR[q * 4 + 0]);
            accR[q * 4 + 1] = fmaf(xv, b.y, accR[q * 4 + 1]);
            accR[q * 4 + 2] = fmaf(xv, b.z, accR[q * 4 + 2]);
            accR[q * 4 + 3] = fmaf(xv, b.w, accR[q * 4 + 3]);
        }
    }

    int node = nodeBase + local;
    if (node < n) {
        __half2 hh[8];
#pragma unroll
        for (int q = 0; q < 8; q++)
            hh[q] = __floats2half2_rn(accL[2 * q], accL[2 * q + 1]);
        *(uint4*)&g_xlh[(size_t)node * DD + cg] = *(uint4*)&hh[0];
        *(uint4*)&g_xlh[(size_t)node * DD + cg + 8] = *(uint4*)&hh[4];

        float4* outr = (float4*)&g_xr[(size_t)node * DD + cg];
#pragma unroll
        for (int q = 0; q < 4; q++)
            outr[q] = make_float4(accR[q * 4 + 0], accR[q * 4 + 1], accR[q * 4 + 2], accR[q * 4 + 3]);
    }
}

// ---------------------------------------------------------------------------
// Fused aggregation.
// Lane decomposition: h = lane>>4 (node), sub = (lane>>3)&1 (edge slot),
// cl = lane&7 (channel lane, 8 channels each: j = cl*8).
// All intra-node shfls use the 16-lane half mask (halves diverge!).
// ---------------------------------------------------------------------------
__global__ __launch_bounds__(256) void k_agg(const float* __restrict__ xres,
                                             const float* __restrict__ att,
                                             const float* __restrict__ bias,
                                             const float* __restrict__ gamma,
                                             const float* __restrict__ beta,
                                             float* __restrict__ out, int n) {
    int warp = (blockIdx.x * blockDim.x + threadIdx.x) >> 5;
    int lane = threadIdx.x & 31;
    int h = lane >> 4;
    int l16 = lane & 15;
    int sub = l16 >> 3;
    int cl = lane & 7;
    int d = warp * 2 + h;
    bool valid = d < n;
    int dd = valid ? d : 0;
    int j = cl * 8;
    unsigned m16 = h ? 0xFFFF0000u : 0x0000FFFFu;

    // per-node constants: xr row (8 fp32), att (folded)
    float xr[8], a6[8], a4[8];
    {
        float4 t0 = *(const float4*)&g_xr[(size_t)dd * DD + j];
        float4 t1 = *(const float4*)&g_xr[(size_t)dd * DD + j + 4];
        xr[0] = t0.x; xr[1] = t0.y; xr[2] = t0.z; xr[3] = t0.w;
        xr[4] = t1.x; xr[5] = t1.y; xr[6] = t1.z; xr[7] = t1.w;
        float4 u0 = *(const float4*)(att + j);
        float4 u1 = *(const float4*)(att + j + 4);
        float av[8] = {u0.x, u0.y, u0.z, u0.w, u1.x, u1.y, u1.z, u1.w};
#pragma unroll
        for (int c = 0; c < 8; c++) { a6[c] = 0.6f * av[c]; a4[c] = 0.4f * av[c]; }
    }

    float acc[8];
#pragma unroll
    for (int c = 0; c < 8; c++) acc[c] = 0.f;
    float den = 0.f;

    int begin = valid ? g_rowptr[d] : 0;
    int end = valid ? g_rowptr[d + 1] : 0;

    // ---- self loop: slot 0 contributes, slot 1 masked ----
    {
        uint4 raw = *(const uint4*)&g_xlh[(size_t)dd * DD + j];
        float2 f0 = __half22float2(((const __half2*)&raw)[0]);
        float2 f1 = __half22float2(((const __half2*)&raw)[1]);
        float2 f2 = __half22float2(((const __half2*)&raw)[2]);
        float2 f3 = __half22float2(((const __half2*)&raw)[3]);
        float a[8] = {f0.x, f0.y, f1.x, f1.y, f2.x, f2.y, f3.x, f3.y};
        float part = 0.f;
#pragma unroll
        for (int c = 0; c < 8; c++) {
            float m = a[c] + xr[c];
            part = fmaf(m, a6[c], part);
            part = fmaf(fabsf(m), a4[c], part);
        }
        part += __shfl_xor_sync(m16, part, 1, 16);
        float p = (sub == 0) ? __expf(part) : 0.f;
#pragma unroll
        for (int c = 0; c < 8; c++) acc[c] = fmaf(p, a[c], acc[c]);
        den += p;
    }

    // ---- main edge loop: 2 edges per iteration per node ----
    for (int base = begin; base < end; base += 16) {
        int idx = base + l16;
        int sv = (idx < end) ? g_ssrc[idx] : 0;
        int cnt = end - base;
        if (cnt > 16) cnt = 16;
#pragma unroll 4
        for (int k = 0; k < cnt; k += 2) {
            int s = __shfl_sync(m16, sv, k + sub, 16);
            float flag = (k + sub < cnt) ? 1.f : 0.f;
            uint4 raw = *(const uint4*)&g_xlh[(size_t)s * DD + j];
            float2 f0 = __half22float2(((const __half2*)&raw)[0]);
            float2 f1 = __half22float2(((const __half2*)&raw)[1]);
            float2 f2 = __half22float2(((const __half2*)&raw)[2]);
            float2 f3 = __half22float2(((const __half2*)&raw)[3]);
            float a[8] = {f0.x, f0.y, f1.x, f1.y, f2.x, f2.y, f3.x, f3.y};
            float part = 0.f;
#pragma unroll
            for (int c = 0; c < 8; c++) {
                float m = a[c] + xr[c];
                part = fmaf(m, a6[c], part);
                part = fmaf(fabsf(m), a4[c], part);
            }
            part += __shfl_xor_sync(m16, part, 1, 16);
            float p = __expf(part) * flag;
#pragma unroll
            for (int c = 0; c < 8; c++) acc[c] = fmaf(p, a[c], acc[c]);
            den += p;
        }
    }

    // ---- combine the two edge slots (xor 8 stays within the 16-lane half) ----
#pragma unroll
    for (int c = 0; c < 8; c++) acc[c] += __shfl_xor_sync(m16, acc[c], 8, 16);
    den += __shfl_xor_sync(m16, den, 8, 16);

    if (!valid) return;

    // ---- normalize + bias + residual ----
    float inv = 1.f / den;
    float v[8];
    {
        float4 t0 = *(const float4*)&xres[(size_t)d * DD + j];
        float4 t1 = *(const float4*)&xres[(size_t)d * DD + j + 4];
        float4 b0 = *(const float4*)(bias + j);
        float4 b1 = *(const float4*)(bias + j + 4);
        float xv[8] = {t0.x, t0.y, t0.z, t0.w, t1.x, t1.y, t1.z, t1.w};
        float bi[8] = {b0.x, b0.y, b0.z, b0.w, b1.x, b1.y, b1.z, b1.w};
#pragma unroll
        for (int c = 0; c < 8; c++) v[c] = acc[c] * inv + bi[c] + xv[c];
    }

    // ---- LayerNorm stats over 64 ch (8-lane reduce, dup across sub) ----
    float s = 0.f, s2 = 0.f;
#pragma unroll
    for (int c = 0; c < 8; c++) { s += v[c]; s2 += v[c] * v[c]; }
#pragma unroll
    for (int o = 4; o; o >>= 1) {
        s += __shfl_xor_sync(m16, s, o, 16);
        s2 += __shfl_xor_sync(m16, s2, o, 16);
    }
    float mu = s * (1.f / 64.f);
    float var = s2 * (1.f / 64.f) - mu * mu;
    float rstd = rsqrtf(var + 1e-5f);

    // ---- gamma/beta + exact GeLU on this lane's stored quarter ----
    int off = sub * 4;
    float4 ga = *(const float4*)(gamma + j + off);
    float4 be = *(const float4*)(beta + j + off);
    float y0 = (v[off + 0] - mu) * rstd * ga.x + be.x;
    float y1 = (v[off + 1] - mu) * rstd * ga.y + be.y;
    float y2 = (v[off + 2] - mu) * rstd * ga.z + be.z;
    float y3 = (v[off + 3] - mu) * rstd * ga.w + be.w;

    const float ks = 0.70710678118654752f;
    y0 = 0.5f * y0 * (1.f + erff(y0 * ks));
    y1 = 0.5f * y1 * (1.f + erff(y1 * ks));
    y2 = 0.5f * y2 * (1.f + erff(y2 * ks));
    y3 = 0.5f * y3 * (1.f + erff(y3 * ks));

    *(float4*)&out[(size_t)d * DD + j + off] = make_float4(y0, y1, y2, y3);
}

// ---------------------------------------------------------------------------
extern "C" void kernel_launch(void* const* d_in, const int* in_sizes, int n_in,
                              void* d_out, int out_size) {
    const float* x = (const float*)d_in[0];
    const int* ei = (const int*)d_in[1];   // int32: [src(E), dst(E)]
    const float* Wl = (const float*)d_in[2];
    const float* Wr = (const float*)d_in[3];
    const float* att = (const float*)d_in[4];
    const float* bias = (const float*)d_in[5];
    const float* gamma = (const float*)d_in[6];
    const float* beta = (const float*)d_in[7];

    int n = in_sizes[0] / DD;
    int E = in_sizes[1] / 2;
    int Lnum = in_sizes[2] / (DD * DD);

    float *b0p = nullptr, *b1p = nullptr;
    cudaGetSymbolAddress((void**)&b0p, g_b0);
    cudaGetSymbolAddress((void**)&b1p, g_b1);

    // ---- build CSR (dst-sorted edges) ----
    int nbScan = (n + SCAN_TILE - 1) / SCAN_TILE;
    k_cntzero<<<(n + 255) / 256, 256>>>(n);
    k_hist<<<(E + 255) / 256, 256>>>(ei, E);
    k_scan1<<<nbScan, SCAN_BLK>>>(n);
    k_scan2<<<1, 1024>>>(nbScan);
    k_scan3<<<(n + 1 + 255) / 256, 256>>>(n, E);
    k_scatter<<<(E + 255) / 256, 256>>>(ei, E);

    // ---- layers ----
    const float* cur = x;
    int aggBlocks = (n + 15) / 16;  // 16 nodes per 256-thread block
    for (int i = 0; i < Lnum; i++) {
        k_gemm<<<(n + 63) / 64, 256>>>(cur, Wl + (size_t)i * DD * DD,
                                       Wr + (size_t)i * DD * DD, n);

        float* outp;
        if (i == Lnum - 1) outp = (float*)d_out;
        else outp = (i & 1) ? b1p : b0p;

        k_agg<<<aggBlocks, 256>>>(cur, att + (size_t)i * DD,
                                  bias + (size_t)i * DD,
                                  gamma + (size_t)i * DD,
                                  beta + (size_t)i * DD,
                                  outp, n);
        cur = outp;
    }
}